// round 5
// baseline (speedup 1.0000x reference)
#include <cuda_runtime.h>
#include <cuda_bf16.h>
#include <cstdint>

#define N_NODES 50000
#define N_EDGES 800000
#define DIM     128

#define BNT      32                                 // nodes per tile
#define N_TILES  ((N_NODES + BNT - 1) / BNT)        // 1563 (tail tile: 16)
#define BR_THREADS 256
#define BR_GRID  296                                // persistent, 2/SM
// SMEM: W 64KB + X 16KB + bias/scale/offset 1.5KB + LN partials 2KB
#define BR_SMEM (65536 + 16384 + 3*512 + BNT*8*8)

using u64 = unsigned long long;

__device__ __forceinline__ void ffma2(u64& d, u64 a, u64 b) {
    asm("fma.rn.f32x2 %0, %1, %2, %0;" : "+l"(d) : "l"(a), "l"(b));
}
__device__ __forceinline__ float2 unpack2(u64 v) {
    float2 r;
    asm("mov.b64 {%0,%1}, %2;" : "=f"(r.x), "=f"(r.y) : "l"(v));
    return r;
}

__device__ float g_neigh[(size_t)N_NODES * DIM];

// ---------------------------------------------------------------------------
__global__ void zero_kernel(float4* __restrict__ p, int n4) {
    int i = blockIdx.x * blockDim.x + threadIdx.x;
    if (i < n4) p[i] = make_float4(0.f, 0.f, 0.f, 0.f);
}

// ---------------------------------------------------------------------------
// edge scatter: one warp per edge, lane = float4 of 4 dims. LTS-bound.
// ---------------------------------------------------------------------------
__global__ void scatter_kernel(const float* __restrict__ feat,
                               const int*   __restrict__ erow,
                               const int*   __restrict__ ecol,
                               const float* __restrict__ eval_,
                               float*       __restrict__ neigh) {
    int warp_id = (blockIdx.x * blockDim.x + threadIdx.x) >> 5;
    int lane    = threadIdx.x & 31;
    if (warp_id >= N_EDGES) return;
    int   r = erow[warp_id];
    int   c = ecol[warp_id];
    float v = eval_[warp_id];

    const float4* src = (const float4*)(feat + (size_t)c * DIM);
    float4 x = src[lane];
    float4 y;
    y.x = x.x * v; y.y = x.y * v; y.z = x.z * v; y.w = x.w * v;

    float* dst = neigh + (size_t)r * DIM + lane * 4;
    asm volatile("red.global.add.v4.f32 [%0], {%1,%2,%3,%4};"
                 :: "l"(dst), "f"(y.x), "f"(y.y), "f"(y.z), "f"(y.w)
                 : "memory");
}

// ---------------------------------------------------------------------------
// fused branch: out (+)= LN(relu(X @ W^T + b)) * scale + offset
//
// Persistent CTAs (W loaded once). CTA tile = 32 nodes x 128 dims; 8 warps
// each own 16 dims; warp tile 32x32. Thread (mi = lane&7, nj = lane>>3) owns
// 4 nodes x 4 dims; accumulators packed over K (fma.rn.f32x2) = 16 u64 =
// 32 regs, leaving ptxas room to pipeline the LDS latency.
// Per k4: 4 X LDS.128 (8 distinct rows, 4-way bcast, 1 phase each) +
// 4 W LDS.128 (4 distinct rows, 8-way bcast, 1 phase each) feed 32 FFMA2:
// fma-pipe demand (256 cyc/SM @16w) 2x the crossbar (128 cyc) -> fma-bound.
// LN: shuffle over nj (xor 8,16) + cross-warp partials in SMEM.
// ---------------------------------------------------------------------------
template<bool ACC>
__global__ void __launch_bounds__(BR_THREADS, 2) branch_kernel(
    const float* __restrict__ X, const float* __restrict__ W,
    const float* __restrict__ bias, const float* __restrict__ scale,
    const float* __restrict__ offset, int so, float* __restrict__ out)
{
    extern __shared__ char smem[];
    ulonglong2* sW  = (ulonglong2*)smem;                    // [128][32] swizzled
    ulonglong2* sX  = (ulonglong2*)(smem + 65536);          // [32][32]  swizzled
    float*      sB  = (float*)(smem + 65536 + 16384);       // 128
    float*      sS  = sB + 128;
    float*      sO  = sS + 128;
    float2*     sPQ = (float2*)(sO + 128);                  // [32][8]

    const int tid  = threadIdx.x;
    const int lane = tid & 31;
    const int wid  = tid >> 5;
    const int mi   = lane & 7;         // node sub-group
    const int nj   = lane >> 3;        // dim sub-group
    const int rb   = mi * 4;           // local node base (4 nodes)
    const int j0   = wid * 16 + nj * 4;// output-dim base (4 dims)
    const int wsel = (j0 >> 2) & 7;    // W swizzle selector (same for j0..j0+3)

    // W swizzled: row j, chunk k4 at (j<<5) | (k4 ^ ((j>>2)&7)).
    const ulonglong2* Wg = (const ulonglong2*)W;
    for (int i = tid; i < DIM * 32; i += BR_THREADS) {
        int j = i >> 5, k4 = i & 31;
        sW[(j << 5) | (k4 ^ ((j >> 2) & 7))] = Wg[i];
    }
    if (tid < 32)       ((float4*)sB)[tid]      = ((const float4*)bias)[tid];
    else if (tid < 64)  ((float4*)sS)[tid - 32] = ((const float4*)(scale  + so))[tid - 32];
    else if (tid < 96)  ((float4*)sO)[tid - 64] = ((const float4*)(offset + so))[tid - 64];

    const float4 bv = make_float4(0.f, 0.f, 0.f, 0.f); (void)bv;

    for (int tile = blockIdx.x; tile < N_TILES; tile += BR_GRID) {
        const int gbase = tile * BNT;

        // X swizzled: row r, chunk k4 at (r<<5) | (k4 ^ ((r>>2)&7)); clamp tail.
        for (int i = tid; i < BNT * 32; i += BR_THREADS) {
            int r = i >> 5, k4 = i & 31;
            int gr = gbase + r; if (gr >= N_NODES) gr = N_NODES - 1;
            sX[(r << 5) | (k4 ^ ((r >> 2) & 7))] =
                ((const ulonglong2*)X)[(size_t)gr * 32 + k4];
        }
        __syncthreads();   // sX (and, first iter, sW/consts) visible

        u64 acc[4][4];
#pragma unroll
        for (int m = 0; m < 4; m++)
#pragma unroll
            for (int d = 0; d < 4; d++) acc[m][d] = 0ull;

#pragma unroll 4
        for (int k4 = 0; k4 < 32; k4++) {
            const int kx = k4 ^ mi;
            const int kw = k4 ^ wsel;
            ulonglong2 x0 = sX[((rb + 0) << 5) | kx];
            ulonglong2 x1 = sX[((rb + 1) << 5) | kx];
            ulonglong2 x2 = sX[((rb + 2) << 5) | kx];
            ulonglong2 x3 = sX[((rb + 3) << 5) | kx];
#pragma unroll
            for (int d = 0; d < 4; d++) {
                ulonglong2 w = sW[((j0 + d) << 5) | kw];
                ffma2(acc[0][d], w.x, x0.x); ffma2(acc[0][d], w.y, x0.y);
                ffma2(acc[1][d], w.x, x1.x); ffma2(acc[1][d], w.y, x1.y);
                ffma2(acc[2][d], w.x, x2.x); ffma2(acc[2][d], w.y, x2.y);
                ffma2(acc[3][d], w.x, x3.x); ffma2(acc[3][d], w.y, x3.y);
            }
        }

        // ReLU + per-node partials over this thread's 4 dims
        float h[4][4];
        float sp[4], qp[4];
#pragma unroll
        for (int m = 0; m < 4; m++) {
            float s = 0.f, q = 0.f;
#pragma unroll
            for (int d = 0; d < 4; d++) {
                float2 p = unpack2(acc[m][d]);
                float v = fmaxf(p.x + p.y + sB[j0 + d], 0.f);
                h[m][d] = v;
                s += v; q = fmaf(v, v, q);
            }
            sp[m] = s; qp[m] = q;
        }
        // reduce over nj (xor 8, 16) -> sums over this warp's 16 dims
#pragma unroll
        for (int m = 0; m < 4; m++) {
            sp[m] += __shfl_xor_sync(0xffffffffu, sp[m], 8);
            qp[m] += __shfl_xor_sync(0xffffffffu, qp[m], 8);
            sp[m] += __shfl_xor_sync(0xffffffffu, sp[m], 16);
            qp[m] += __shfl_xor_sync(0xffffffffu, qp[m], 16);
        }
        if (nj == 0) {
#pragma unroll
            for (int m = 0; m < 4; m++)
                sPQ[(rb + m) * 8 + wid] = make_float2(sp[m], qp[m]);
        }
        __syncthreads();   // sPQ visible; all sX reads done

        const float4 sc = *(const float4*)(sS + j0);
        const float4 of = *(const float4*)(sO + j0);

#pragma unroll
        for (int m = 0; m < 4; m++) {
            const int r = rb + m;
            float s = 0.f, q = 0.f;
#pragma unroll
            for (int wq = 0; wq < 8; wq++) {
                float2 t = sPQ[r * 8 + wq];
                s += t.x; q += t.y;
            }
            float mean = s * (1.f / DIM);
            float var  = q * (1.f / DIM) - mean * mean + 1e-9f;
            float rs   = rsqrtf(var);

            int gnode = gbase + r;
            if (gnode < N_NODES) {
                float4 rv;
                rv.x = (h[m][0] - mean) * rs * sc.x + of.x;
                rv.y = (h[m][1] - mean) * rs * sc.y + of.y;
                rv.z = (h[m][2] - mean) * rs * sc.z + of.z;
                rv.w = (h[m][3] - mean) * rs * sc.w + of.w;

                float4* op = (float4*)(out + (size_t)gnode * DIM + j0);
                if (ACC) {
                    float4 p = *op;
                    rv.x += p.x; rv.y += p.y; rv.z += p.z; rv.w += p.w;
                }
                *op = rv;
            }
        }
        __syncthreads();   // sPQ readers done before next tile overwrites
    }
}

// ---------------------------------------------------------------------------
struct ForkResources {
    cudaStream_t s2  = nullptr;
    cudaEvent_t  ev1 = nullptr, ev2 = nullptr;
    bool ok = false;
    ForkResources() {
        if (cudaStreamCreateWithFlags(&s2, cudaStreamNonBlocking) != cudaSuccess) return;
        if (cudaEventCreateWithFlags(&ev1, cudaEventDisableTiming) != cudaSuccess) return;
        if (cudaEventCreateWithFlags(&ev2, cudaEventDisableTiming) != cudaSuccess) return;
        ok = true;
    }
};
static ForkResources g_fork;

// ---------------------------------------------------------------------------
// stream0: zero -> scatter ----\
// s2:      branch_self ---------- join -> branch_neigh(ACC)
// ---------------------------------------------------------------------------
extern "C" void kernel_launch(void* const* d_in, const int* in_sizes, int n_in,
                              void* d_out, int out_size) {
    const float* feat_in  = (const float*)d_in[0];
    const int*   edge_row = (const int*)  d_in[1];
    const int*   edge_col = (const int*)  d_in[2];
    const float* edge_val = (const float*)d_in[3];
    const float* W_self   = (const float*)d_in[4];
    const float* b_self   = (const float*)d_in[5];
    const float* W_neigh  = (const float*)d_in[6];
    const float* b_neigh  = (const float*)d_in[7];
    const float* scale    = (const float*)d_in[8];
    const float* offset   = (const float*)d_in[9];
    float* out = (float*)d_out;

    float* neigh = nullptr;
    cudaGetSymbolAddress((void**)&neigh, g_neigh);

    cudaFuncSetAttribute(branch_kernel<false>,
                         cudaFuncAttributeMaxDynamicSharedMemorySize, BR_SMEM);
    cudaFuncSetAttribute(branch_kernel<true>,
                         cudaFuncAttributeMaxDynamicSharedMemorySize, BR_SMEM);

    const int n4 = N_NODES * DIM / 4;
    const int scatter_blocks = (N_EDGES * 32) / 256;

    if (g_fork.ok) {
        cudaEventRecord(g_fork.ev1, 0);
        cudaStreamWaitEvent(g_fork.s2, g_fork.ev1, 0);

        branch_kernel<false><<<BR_GRID, BR_THREADS, BR_SMEM, g_fork.s2>>>(
            feat_in, W_self, b_self, scale, offset, 0, out);

        zero_kernel<<<(n4 + 255) / 256, 256>>>((float4*)neigh, n4);
        scatter_kernel<<<scatter_blocks, 256>>>(feat_in, edge_row, edge_col, edge_val, neigh);

        cudaEventRecord(g_fork.ev2, g_fork.s2);
        cudaStreamWaitEvent(0, g_fork.ev2, 0);

        branch_kernel<true><<<BR_GRID, BR_THREADS, BR_SMEM>>>(
            neigh, W_neigh, b_neigh, scale, offset, DIM, out);
    } else {
        zero_kernel<<<(n4 + 255) / 256, 256>>>((float4*)neigh, n4);
        branch_kernel<false><<<BR_GRID, BR_THREADS, BR_SMEM>>>(
            feat_in, W_self, b_self, scale, offset, 0, out);
        scatter_kernel<<<scatter_blocks, 256>>>(feat_in, edge_row, edge_col, edge_val, neigh);
        branch_kernel<true><<<BR_GRID, BR_THREADS, BR_SMEM>>>(
            neigh, W_neigh, b_neigh, scale, offset, DIM, out);
    }
}

// round 7
// speedup vs baseline: 1.4001x; 1.4001x over previous
#include <cuda_runtime.h>
#include <cuda_bf16.h>
#include <cstdint>

#define N_NODES 50000
#define N_EDGES 800000
#define DIM     128

#define TILE_M   128
#define N_TILES  ((N_NODES + TILE_M - 1) / TILE_M)   // 391

// ---------------- SMEM layout (bytes, dynamic) ----------------------------
// bf16 tiles are [128 rows][128 cols], 256B/row, 16B-chunk XOR swizzle.
#define OFF_XHI   0
#define OFF_XLO   32768
#define OFF_WHI   65536
#define OFF_WLO   98304
#define OFF_CONST 131072                 // bias/scale/offset: 3 x 512B
#define GEMM_SMEM (131072 + 1536)
// fp32 stage [128][132] (67584B) overlays XHI/XLO/start of WHI after mainloop
#define STAGE_STRIDE 132

__device__ float g_neigh[(size_t)N_NODES * DIM];

// ---------------------------------------------------------------------------
__global__ void zero_kernel(float4* __restrict__ p, int n4) {
    int i = blockIdx.x * blockDim.x + threadIdx.x;
    if (i < n4) p[i] = make_float4(0.f, 0.f, 0.f, 0.f);
}

// edge scatter: one warp per edge, lane = float4 of 4 dims. LTS-bound.
__global__ void scatter_kernel(const float* __restrict__ feat,
                               const int*   __restrict__ erow,
                               const int*   __restrict__ ecol,
                               const float* __restrict__ eval_,
                               float*       __restrict__ neigh) {
    int warp_id = (blockIdx.x * blockDim.x + threadIdx.x) >> 5;
    int lane    = threadIdx.x & 31;
    if (warp_id >= N_EDGES) return;
    int   r = erow[warp_id];
    int   c = ecol[warp_id];
    float v = eval_[warp_id];
    const float4* src = (const float4*)(feat + (size_t)c * DIM);
    float4 x = src[lane];
    float4 y;
    y.x = x.x * v; y.y = x.y * v; y.z = x.z * v; y.w = x.w * v;
    float* dst = neigh + (size_t)r * DIM + lane * 4;
    asm volatile("red.global.add.v4.f32 [%0], {%1,%2,%3,%4};"
                 :: "l"(dst), "f"(y.x), "f"(y.y), "f"(y.z), "f"(y.w) : "memory");
}

// ---------------------------------------------------------------------------
__device__ __forceinline__ uint32_t smem_u32(const void* p) {
    uint32_t a;
    asm("{ .reg .u64 t; cvta.to.shared.u64 t, %1; cvt.u32.u64 %0, t; }" : "=r"(a) : "l"(p));
    return a;
}
__device__ __forceinline__ void ldsm_x4(uint32_t& r0, uint32_t& r1,
                                        uint32_t& r2, uint32_t& r3, uint32_t a) {
    asm volatile("ldmatrix.sync.aligned.m8n8.x4.shared.b16 {%0,%1,%2,%3}, [%4];"
                 : "=r"(r0), "=r"(r1), "=r"(r2), "=r"(r3) : "r"(a));
}
__device__ __forceinline__ void mma_bf16(float* c, const uint32_t* a,
                                         uint32_t b0, uint32_t b1) {
    asm volatile("mma.sync.aligned.m16n8k16.row.col.f32.bf16.bf16.f32 "
                 "{%0,%1,%2,%3}, {%4,%5,%6,%7}, {%8,%9}, {%0,%1,%2,%3};"
                 : "+f"(c[0]), "+f"(c[1]), "+f"(c[2]), "+f"(c[3])
                 : "r"(a[0]), "r"(a[1]), "r"(a[2]), "r"(a[3]), "r"(b0), "r"(b1));
}

// bf16 tile addressing: row r, col k. 16B chunk index (k>>3) XOR-swizzled by (r&7).
__device__ __forceinline__ uint32_t bt_off(int r, int k0 /* mult of 8 */) {
    return (uint32_t)(r * 256 + ((((k0 >> 3) ^ (r & 7)) & 15) << 4));
}
// ldmatrix address generators (canonical m16n8k16 patterns)
__device__ __forceinline__ uint32_t a_addr(uint32_t base, int m0, int kb, int lane) {
    int row = m0 + (lane & 15);
    int chunk = (kb >> 3) + (lane >> 4);
    return base + row * 256 + (((chunk ^ (row & 7)) & 15) << 4);
}
__device__ __forceinline__ uint32_t b_addr(uint32_t base, int n0, int kb, int lane) {
    int row = n0 + (lane & 7) + ((lane >> 4) << 3);
    int chunk = (kb >> 3) + ((lane >> 3) & 1);
    return base + row * 256 + (((chunk ^ (row & 7)) & 15) << 4);
}

// split one 8-float chunk into bf16 hi/lo and store swizzled
__device__ __forceinline__ void split_store8(const float* src, char* hi_base, char* lo_base,
                                             int r, int k0) {
    float4 a = ((const float4*)src)[0];
    float4 b = ((const float4*)src)[1];
    float v[8] = {a.x, a.y, a.z, a.w, b.x, b.y, b.z, b.w};
    uint32_t hp[4], lp[4];
#pragma unroll
    for (int e = 0; e < 4; e++) {
        __nv_bfloat16 h0 = __float2bfloat16(v[2 * e]);
        __nv_bfloat16 h1 = __float2bfloat16(v[2 * e + 1]);
        __nv_bfloat16 l0 = __float2bfloat16(v[2 * e]     - __bfloat162float(h0));
        __nv_bfloat16 l1 = __float2bfloat16(v[2 * e + 1] - __bfloat162float(h1));
        __nv_bfloat162 hh = __halves2bfloat162(h0, h1);
        __nv_bfloat162 ll = __halves2bfloat162(l0, l1);
        hp[e] = *(uint32_t*)&hh;
        lp[e] = *(uint32_t*)&ll;
    }
    uint32_t o = bt_off(r, k0);
    *(uint4*)(hi_base + o) = make_uint4(hp[0], hp[1], hp[2], hp[3]);
    *(uint4*)(lo_base + o) = make_uint4(lp[0], lp[1], lp[2], lp[3]);
}

// ---------------------------------------------------------------------------
// Tensor branch via mma.sync bf16 3-term split:
//   out (+)= LN(relu(X @ W^T + b)) * scale + offset
// CTA = 128-node tile. 8 warps: mw = wid&1 (m half), nw = wid>>1 (n quarter);
// warp tile 64(m) x 32(n) = 4x4 m16n8 fragments. Mainloop per k16 step:
// 12 ldmatrix.x4 + 48 HMMA. Epilogue: fragments -> padded fp32 SMEM stage,
// LN per row (2 threads/row + shfl), fused affine + optional accumulate.
// ---------------------------------------------------------------------------
template<bool ACC>
__global__ void __launch_bounds__(256, 1) mma_branch(
    const float* __restrict__ X, const float* __restrict__ W,
    const float* __restrict__ bias, const float* __restrict__ scale,
    const float* __restrict__ offset, int so, float* __restrict__ out)
{
    extern __shared__ char smem[];
    const uint32_t sb = smem_u32(smem);
    const int tid  = threadIdx.x;
    const int wid  = tid >> 5;
    const int lane = tid & 31;
    const int mw   = wid & 1;
    const int nw   = wid >> 1;
    const int gbase = blockIdx.x * TILE_M;

    // ---- convert W and X tile to bf16 hi/lo (swizzled) ----
    for (int i = tid; i < 2048; i += 256) {
        int r = i >> 4, k0 = (i & 15) << 3;
        split_store8(W + r * DIM + k0, smem + OFF_WHI, smem + OFF_WLO, r, k0);
    }
    for (int i = tid; i < 2048; i += 256) {
        int r = i >> 4, k0 = (i & 15) << 3;
        int gr = gbase + r; if (gr >= N_NODES) gr = N_NODES - 1;
        split_store8(X + (size_t)gr * DIM + k0, smem + OFF_XHI, smem + OFF_XLO, r, k0);
    }
    float* sB = (float*)(smem + OFF_CONST);
    float* sS = sB + 128;
    float* sO = sS + 128;
    if (tid < 32)       ((float4*)sB)[tid]      = ((const float4*)bias)[tid];
    else if (tid < 64)  ((float4*)sS)[tid - 32] = ((const float4*)(scale  + so))[tid - 32];
    else if (tid < 96)  ((float4*)sO)[tid - 64] = ((const float4*)(offset + so))[tid - 64];
    __syncthreads();

    // ---- mainloop ----
    float acc[4][4][4];
#pragma unroll
    for (int mt = 0; mt < 4; mt++)
#pragma unroll
        for (int nt = 0; nt < 4; nt++)
#pragma unroll
            for (int e = 0; e < 4; e++) acc[mt][nt][e] = 0.f;

    const uint32_t xhi = sb + OFF_XHI, xlo = sb + OFF_XLO;
    const uint32_t whi = sb + OFF_WHI, wlo = sb + OFF_WLO;

#pragma unroll
    for (int kb8 = 0; kb8 < 8; kb8++) {
        const int kb = kb8 * 16;
        uint32_t ahi[4][4], alo[4][4], bhi[4][2], blo[4][2];
#pragma unroll
        for (int mt = 0; mt < 4; mt++) {
            uint32_t aa = a_addr(xhi, mw * 64 + mt * 16, kb, lane);
            ldsm_x4(ahi[mt][0], ahi[mt][1], ahi[mt][2], ahi[mt][3], aa);
            uint32_t al = a_addr(xlo, mw * 64 + mt * 16, kb, lane);
            ldsm_x4(alo[mt][0], alo[mt][1], alo[mt][2], alo[mt][3], al);
        }
#pragma unroll
        for (int p = 0; p < 2; p++) {
            uint32_t ba = b_addr(whi, nw * 32 + p * 16, kb, lane);
            ldsm_x4(bhi[2*p][0], bhi[2*p][1], bhi[2*p+1][0], bhi[2*p+1][1], ba);
            uint32_t bb = b_addr(wlo, nw * 32 + p * 16, kb, lane);
            ldsm_x4(blo[2*p][0], blo[2*p][1], blo[2*p+1][0], blo[2*p+1][1], bb);
        }
#pragma unroll
        for (int mt = 0; mt < 4; mt++)
#pragma unroll
            for (int nt = 0; nt < 4; nt++) {
                mma_bf16(acc[mt][nt], ahi[mt], bhi[nt][0], bhi[nt][1]);
                mma_bf16(acc[mt][nt], ahi[mt], blo[nt][0], blo[nt][1]);
                mma_bf16(acc[mt][nt], alo[mt], bhi[nt][0], bhi[nt][1]);
            }
    }
    __syncthreads();   // all ldmatrix reads done; safe to overlay stage

    // ---- fragments -> fp32 stage [128][STAGE_STRIDE] ----
    float* stage = (float*)smem;   // overlays XHI/XLO(+WHI head)
    {
        const int rsub = lane >> 2;
        const int csub = (lane & 3) * 2;
#pragma unroll
        for (int mt = 0; mt < 4; mt++)
#pragma unroll
            for (int nt = 0; nt < 4; nt++) {
                int row = mw * 64 + mt * 16 + rsub;
                int col = nw * 32 + nt * 8 + csub;
                *(float2*)(stage + row * STAGE_STRIDE + col) =
                    make_float2(acc[mt][nt][0], acc[mt][nt][1]);
                *(float2*)(stage + (row + 8) * STAGE_STRIDE + col) =
                    make_float2(acc[mt][nt][2], acc[mt][nt][3]);
            }
    }
    __syncthreads();

    // ---- LN + affine + optional accumulate; 2 threads per row ----
    {
        const int r  = tid >> 1;
        const int hh = tid & 1;
        float* row = stage + r * STAGE_STRIDE + hh * 64;
        float s = 0.f, q = 0.f;
#pragma unroll
        for (int i = 0; i < 16; i++) {
            float4 v = ((float4*)row)[i];
            const int c = hh * 64 + i * 4;
            v.x = fmaxf(v.x + sB[c + 0], 0.f);
            v.y = fmaxf(v.y + sB[c + 1], 0.f);
            v.z = fmaxf(v.z + sB[c + 2], 0.f);
            v.w = fmaxf(v.w + sB[c + 3], 0.f);
            ((float4*)row)[i] = v;
            s += v.x + v.y + v.z + v.w;
            q = fmaf(v.x, v.x, q); q = fmaf(v.y, v.y, q);
            q = fmaf(v.z, v.z, q); q = fmaf(v.w, v.w, q);
        }
        s += __shfl_xor_sync(0xffffffffu, s, 1);
        q += __shfl_xor_sync(0xffffffffu, q, 1);
        float mean = s * (1.f / DIM);
        float var  = q * (1.f / DIM) - mean * mean + 1e-9f;
        float rs   = rsqrtf(var);

        const int g = gbase + r;
        if (g < N_NODES) {
            float4* op = (float4*)(out + (size_t)g * DIM + hh * 64);
#pragma unroll
            for (int i = 0; i < 16; i++) {
                float4 v = ((float4*)row)[i];
                const int c = hh * 64 + i * 4;
                float4 rv;
                rv.x = (v.x - mean) * rs * sS[c + 0] + sO[c + 0];
                rv.y = (v.y - mean) * rs * sS[c + 1] + sO[c + 1];
                rv.z = (v.z - mean) * rs * sS[c + 2] + sO[c + 2];
                rv.w = (v.w - mean) * rs * sS[c + 3] + sO[c + 3];
                if (ACC) {
                    float4 p = op[i];
                    rv.x += p.x; rv.y += p.y; rv.z += p.z; rv.w += p.w;
                }
                op[i] = rv;
            }
        }
    }
}

// ---------------------------------------------------------------------------
struct ForkResources {
    cudaStream_t s2  = nullptr;
    cudaEvent_t  ev1 = nullptr, ev2 = nullptr;
    bool ok = false;
    ForkResources() {
        if (cudaStreamCreateWithFlags(&s2, cudaStreamNonBlocking) != cudaSuccess) return;
        if (cudaEventCreateWithFlags(&ev1, cudaEventDisableTiming) != cudaSuccess) return;
        if (cudaEventCreateWithFlags(&ev2, cudaEventDisableTiming) != cudaSuccess) return;
        ok = true;
    }
};
static ForkResources g_fork;

// ---------------------------------------------------------------------------
// stream0: zero -> scatter ----\
// s2:      mma_self ------------ join -> mma_neigh(ACC)
// ---------------------------------------------------------------------------
extern "C" void kernel_launch(void* const* d_in, const int* in_sizes, int n_in,
                              void* d_out, int out_size) {
    const float* feat_in  = (const float*)d_in[0];
    const int*   edge_row = (const int*)  d_in[1];
    const int*   edge_col = (const int*)  d_in[2];
    const float* edge_val = (const float*)d_in[3];
    const float* W_self   = (const float*)d_in[4];
    const float* b_self   = (const float*)d_in[5];
    const float* W_neigh  = (const float*)d_in[6];
    const float* b_neigh  = (const float*)d_in[7];
    const float* scale    = (const float*)d_in[8];
    const float* offset   = (const float*)d_in[9];
    float* out = (float*)d_out;

    float* neigh = nullptr;
    cudaGetSymbolAddress((void**)&neigh, g_neigh);

    cudaFuncSetAttribute(mma_branch<false>,
                         cudaFuncAttributeMaxDynamicSharedMemorySize, GEMM_SMEM);
    cudaFuncSetAttribute(mma_branch<true>,
                         cudaFuncAttributeMaxDynamicSharedMemorySize, GEMM_SMEM);

    const int n4 = N_NODES * DIM / 4;
    const int scatter_blocks = (N_EDGES * 32) / 256;

    if (g_fork.ok) {
        cudaEventRecord(g_fork.ev1, 0);
        cudaStreamWaitEvent(g_fork.s2, g_fork.ev1, 0);

        mma_branch<false><<<N_TILES, 256, GEMM_SMEM, g_fork.s2>>>(
            feat_in, W_self, b_self, scale, offset, 0, out);

        zero_kernel<<<(n4 + 255) / 256, 256>>>((float4*)neigh, n4);
        scatter_kernel<<<scatter_blocks, 256>>>(feat_in, edge_row, edge_col, edge_val, neigh);

        cudaEventRecord(g_fork.ev2, g_fork.s2);
        cudaStreamWaitEvent(0, g_fork.ev2, 0);

        mma_branch<true><<<N_TILES, 256, GEMM_SMEM>>>(
            neigh, W_neigh, b_neigh, scale, offset, DIM, out);
    } else {
        zero_kernel<<<(n4 + 255) / 256, 256>>>((float4*)neigh, n4);
        mma_branch<false><<<N_TILES, 256, GEMM_SMEM>>>(
            feat_in, W_self, b_self, scale, offset, 0, out);
        scatter_kernel<<<scatter_blocks, 256>>>(feat_in, edge_row, edge_col, edge_val, neigh);
        mma_branch<true><<<N_TILES, 256, GEMM_SMEM>>>(
            neigh, W_neigh, b_neigh, scale, offset, DIM, out);
    }
}